// round 12
// baseline (speedup 1.0000x reference)
#include <cuda_runtime.h>
#include <math.h>
#include <stdint.h>

#define B_  4
#define S_  2048
#define D_  1024
#define H_  16
#define DK_ 64
#define DV_ 64

// Scratch (alloc-free rule: __device__ globals)
__device__ float g_q[B_*H_*S_*DK_];   // [B,H,S,DK] fp32 (raw)
__device__ float g_k[B_*H_*S_*DK_];   // [B,H,S,DK] tf32-rounded
__device__ float g_v[B_*H_*S_*DV_];   // [B,H,S,DV] tf32-rounded
__device__ float g_a[B_*S_*H_*DV_];   // [B,S,H*DV] tf32-rounded
__device__ float g_qc[B_*S_*D_];      // rounded copy of query
__device__ float g_kc[B_*S_*D_];      // rounded copy of key
__device__ float g_vc[B_*S_*D_];      // rounded copy of value
__device__ float g_wqr[D_*H_*DK_];
__device__ float g_wkr[D_*H_*DK_];
__device__ float g_wvr[D_*H_*DV_];
__device__ float g_wor[H_*DV_*D_];
__device__ int   g_idx[B_*S_];        // compacted unmasked key indices
__device__ int   g_cnt[B_];           // count per batch

__device__ __forceinline__ float to_tf32(float x) {
    float r;
    asm("cvt.rna.tf32.f32 %0, %1;" : "=f"(r) : "f"(x));
    return r;
}

__device__ __forceinline__ void mma_tf32(float& d0, float& d1, float& d2, float& d3,
                                         uint32_t a0, uint32_t a1, uint32_t a2, uint32_t a3,
                                         uint32_t b0, uint32_t b1)
{
    asm volatile(
        "mma.sync.aligned.m16n8k8.row.col.f32.tf32.tf32.f32 "
        "{%0,%1,%2,%3}, {%4,%5,%6,%7}, {%8,%9}, {%0,%1,%2,%3};"
        : "+f"(d0), "+f"(d1), "+f"(d2), "+f"(d3)
        : "r"(a0), "r"(a1), "r"(a2), "r"(a3), "r"(b0), "r"(b1));
}

__device__ __forceinline__ void ldsm_x4(uint32_t& r0, uint32_t& r1, uint32_t& r2, uint32_t& r3,
                                        uint32_t addr)
{
    asm volatile("ldmatrix.sync.aligned.m8n8.x4.shared.b16 {%0,%1,%2,%3}, [%4];"
                 : "=r"(r0), "=r"(r1), "=r"(r2), "=r"(r3) : "r"(addr));
}

__device__ __forceinline__ void cp16(uint32_t dst_smem, const void* src) {
    asm volatile("cp.async.cg.shared.global [%0], [%1], 16;" :: "r"(dst_smem), "l"(src));
}
__device__ __forceinline__ void cp_commit() {
    asm volatile("cp.async.commit_group;");
}
template<int N>
__device__ __forceinline__ void cp_wait() {
    asm volatile("cp.async.wait_group %0;" :: "n"(N));
}

// ---------------------------------------------------------------------------
// Mask compaction: one warp per batch. Keys with mask==0 survive.
// ---------------------------------------------------------------------------
__global__ void compact_k(const int* __restrict__ mask)
{
    const int b = blockIdx.x;
    const int lane = threadIdx.x;
    int c = 0;
    for (int base = 0; base < S_; base += 32) {
        int mv = mask[b * S_ + base + lane];
        unsigned ball = __ballot_sync(0xffffffffu, mv == 0);
        int rank = __popc(ball & ((1u << lane) - 1));
        if (mv == 0) g_idx[b * S_ + c + rank] = base + lane;
        c += __popc(ball);
    }
    if (lane == 0) g_cnt[b] = c;
}

// ---------------------------------------------------------------------------
// Pre-round to tf32 (rna), vectorized. blockIdx.y selects the tensor.
// ---------------------------------------------------------------------------
__global__ void round_k(const float* __restrict__ s0, const float* __restrict__ s1,
                        const float* __restrict__ s2, const float* __restrict__ s3,
                        float* __restrict__ d0, float* __restrict__ d1,
                        float* __restrict__ d2, float* __restrict__ d3, int n4)
{
    const int z = blockIdx.y;
    const float* s = (z == 0) ? s0 : (z == 1) ? s1 : (z == 2) ? s2 : s3;
    float*       d = (z == 0) ? d0 : (z == 1) ? d1 : (z == 2) ? d2 : d3;
    const int stride = gridDim.x * blockDim.x;
    for (int i = blockIdx.x * blockDim.x + threadIdx.x; i < n4; i += stride) {
        float4 v = ((const float4*)s)[i];
        v.x = to_tf32(v.x); v.y = to_tf32(v.y);
        v.z = to_tf32(v.z); v.w = to_tf32(v.w);
        ((float4*)d)[i] = v;
    }
}

// ---------------------------------------------------------------------------
// tf32 tensor-core GEMM. Inputs PRE-ROUNDED to tf32 -> no cvt anywhere.
// 3-stage cp.async pipeline, k-step 32, ONE __syncthreads per 32-k iter.
// Dynamic smem 96KB. XOR-swizzled (no padding):
//   A [row][32]: chunk c ^= (row&7)  (8-way; ldmatrix phase -> all 32 banks)
//   B [k][128] : chunk c ^= swk(kr)  (verified conflict-free for b-frags)
// Block tile 128x128, 256 threads = 8 warps (2x4), warp tile 64x32.
// MODE 0: fused QKV (z selects set), scatter-store [B,H,S,64];
//         z=1,2 (K,V) stored tf32-rounded, z=0 (Q) raw fp32.
// MODE 1: single GEMM, row-major store.
// ---------------------------------------------------------------------------
#define KSTEP 32
#define A_STG_BYTES (128 * KSTEP * 4)          // 16384
#define B_STG_BYTES (KSTEP * 128 * 4)          // 16384
#define GEMM_SMEM   (3 * (A_STG_BYTES + B_STG_BYTES))   // 98304

template<int MODE>
__global__ __launch_bounds__(256)
void gemm_tc(const float* __restrict__ A0, const float* __restrict__ A1,
             const float* __restrict__ A2,
             const float* __restrict__ W0, const float* __restrict__ W1,
             const float* __restrict__ W2,
             const float* __restrict__ b0p, const float* __restrict__ b1p,
             const float* __restrict__ b2p,
             float* __restrict__ C0, float* __restrict__ C1, float* __restrict__ C2,
             int M, int N, int K)
{
    extern __shared__ __align__(16) float smem[];

    const int z = (MODE == 0) ? blockIdx.z : 0;
    const float* A    = (z == 0) ? A0 : (z == 1) ? A1 : A2;
    const float* W    = (z == 0) ? W0 : (z == 1) ? W1 : W2;
    const float* bias = (z == 0) ? b0p : (z == 1) ? b1p : b2p;
    float*       C    = (z == 0) ? C0 : (z == 1) ? C1 : C2;

    const int tid  = threadIdx.x;
    const int warp = tid >> 5;
    const int lane = tid & 31;
    const int g    = lane >> 2;
    const int tig  = lane & 3;
    const int wr   = warp >> 2;
    const int wc   = warp & 3;

    const int rBase = blockIdx.y * 128;
    const int cBase = blockIdx.x * 128;

    const uint32_t smb = (uint32_t)__cvta_generic_to_shared(smem);
    uint32_t asb[3], bsb[3];
#pragma unroll
    for (int s = 0; s < 3; s++) {
        asb[s] = smb + s * A_STG_BYTES;
        bsb[s] = smb + 3 * A_STG_BYTES + s * B_STG_BYTES;
    }

    // ldmatrix per-lane: m within 16-row tile, khalf selects k-quad parity
    const int m16   = lane & 15;
    const int khalf = lane >> 4;

    auto issue = [&](int k0, int buf) {
#pragma unroll
        for (int j = 0; j < 4; j++) {
            int idx = tid + j * 256;          // A: 1024 chunks of 16B
            int r   = idx >> 3;
            int c   = idx & 7;
            cp16(asb[buf] + ((r * KSTEP + ((c ^ (r & 7)) << 2)) << 2),
                 A + (size_t)(rBase + r) * K + k0 + c * 4);
        }
#pragma unroll
        for (int j = 0; j < 4; j++) {
            int idx = tid + j * 256;          // B: 1024 chunks
            int kr  = idx >> 5;
            int cc  = idx & 31;
            int swk = ((kr + (kr >> 2)) & 3) << 1;
            cp16(bsb[buf] + ((kr * 128 + ((cc ^ swk) << 2)) << 2),
                 W + (size_t)(k0 + kr) * N + cBase + cc * 4);
        }
        cp_commit();
    };

    float acc[4][4][4];
#pragma unroll
    for (int mt = 0; mt < 4; mt++)
#pragma unroll
        for (int nt = 0; nt < 4; nt++)
#pragma unroll
            for (int r = 0; r < 4; r++) acc[mt][nt][r] = 0.f;

    auto compute = [&](int buf) {
        const uint32_t as = asb[buf];
        const float* bs = (const float*)(smem + (3 * A_STG_BYTES + buf * B_STG_BYTES) / 4);
#pragma unroll
        for (int ks = 0; ks < 4; ks++) {
            const int kb = ks * 8;
            const int kq = ks * 2 + khalf;    // k-quad index 0..7
            uint32_t a[4][4];
#pragma unroll
            for (int mt = 0; mt < 4; mt++) {
                int row = wr * 64 + mt * 16 + m16;
                ldsm_x4(a[mt][0], a[mt][1], a[mt][2], a[mt][3],
                        as + (uint32_t)((row * KSTEP + ((kq ^ (row & 7)) << 2)) << 2));
            }
            int kr0 = kb + tig, kr1 = kb + tig + 4;
            int sw0 = ((kr0 + (kr0 >> 2)) & 3) << 1;
            int sw1 = ((kr1 + (kr1 >> 2)) & 3) << 1;
            uint32_t b[4][2];
#pragma unroll
            for (int nt = 0; nt < 4; nt++) {
                int col = wc * 32 + nt * 8 + g;
                int chi = col >> 2, clo = col & 3;
                b[nt][0] = __float_as_uint(bs[kr0 * 128 + ((chi ^ sw0) << 2) + clo]);
                b[nt][1] = __float_as_uint(bs[kr1 * 128 + ((chi ^ sw1) << 2) + clo]);
            }
#pragma unroll
            for (int mt = 0; mt < 4; mt++)
#pragma unroll
                for (int nt = 0; nt < 4; nt++)
                    mma_tf32(acc[mt][nt][0], acc[mt][nt][1], acc[mt][nt][2], acc[mt][nt][3],
                             a[mt][0], a[mt][1], a[mt][2], a[mt][3],
                             b[nt][0], b[nt][1]);
        }
    };

    const int niter = K / KSTEP;
    issue(0, 0);
    issue(KSTEP, 1);
    for (int i = 0; i < niter; i++) {
        cp_wait<1>();
        __syncthreads();
        compute(i % 3);
        if (i + 2 < niter) issue((i + 2) * KSTEP, (i + 2) % 3);
        else cp_commit();
    }

    // epilogue
#pragma unroll
    for (int mt = 0; mt < 4; mt++) {
#pragma unroll
        for (int nt = 0; nt < 4; nt++) {
#pragma unroll
            for (int half = 0; half < 2; half++) {
                int r = rBase + wr * 64 + mt * 16 + g + half * 8;
                int c = cBase + wc * 32 + nt * 8 + tig * 2;
                float v0 = acc[mt][nt][half * 2 + 0] + bias[c];
                float v1 = acc[mt][nt][half * 2 + 1] + bias[c + 1];
                if (MODE == 0) {
                    if (z != 0) { v0 = to_tf32(v0); v1 = to_tf32(v1); }
                    int bb = r >> 11;
                    int s  = r & 2047;
                    int h  = c >> 6;
                    int dk = c & 63;
                    size_t base = (((size_t)(bb * H_ + h) * S_) + s) * DK_ + dk;
                    C[base]     = v0;
                    C[base + 1] = v1;
                } else {
                    C[(size_t)r * N + c]     = v0;
                    C[(size_t)r * N + c + 1] = v1;
                }
            }
        }
    }
}

// ---------------------------------------------------------------------------
// Tensor-core flash attention over COMPACTED keys.
// 256 threads / 8 warps, 128 q-rows per block (16 per warp).
// tf32 MMA; QK^T error-compensated (Q hi/lo), K/V pre-rounded, K via ldmatrix.
// P (C-layout) converted to A-layout fragments by warp shuffles -- no P smem.
// cp.async double-buffered K/V gather.
// ---------------------------------------------------------------------------
#define KT 32

__global__ __launch_bounds__(256)
void attn_tc(const float* __restrict__ q, const float* __restrict__ k,
             const float* __restrict__ v, float* __restrict__ out)
{
    __shared__ __align__(16) float k_s[2][KT * 68];
    __shared__ __align__(16) float v_s[2][KT * 72];

    const int tid  = threadIdx.x;
    const int warp = tid >> 5;
    const int lane = tid & 31;
    const int g    = lane >> 2;
    const int tig  = lane & 3;

    const int qb = blockIdx.x * 128;
    const int h  = blockIdx.y;
    const int b  = blockIdx.z;

    const int  cnt  = g_cnt[b];
    const int* idxl = g_idx + b * S_;

    const float* qbh = q + ((size_t)(b * H_ + h) * S_) * DK_;
    const float* kbh = k + ((size_t)(b * H_ + h) * S_) * DK_;
    const float* vbh = v + ((size_t)(b * H_ + h) * S_) * DV_;

    const uint32_t ksb[2] = { (uint32_t)__cvta_generic_to_shared(k_s[0]),
                              (uint32_t)__cvta_generic_to_shared(k_s[1]) };
    const uint32_t vsb[2] = { (uint32_t)__cvta_generic_to_shared(v_s[0]),
                              (uint32_t)__cvta_generic_to_shared(v_s[1]) };

    // K ldmatrix per-lane offset: n = (lane>>4)*8 + (lane&7), k = ((lane>>3)&1)*4
    const uint32_t koff = (((((lane >> 4) << 3) + (lane & 7)) * 68) + (((lane >> 3) & 1) << 2)) * 4;

    // P shuffle sources: col tig held by lane 4g+(tig>>1); col tig+4 by +2
    const int psrc0 = (lane & ~3) | (tig >> 1);
    const int psrc1 = psrc0 + 2;
    const bool podd = (tig & 1);

    const int nTiles = (cnt + KT - 1) / KT;

    auto issue_tile = [&](int t, int buf) {
#pragma unroll
        for (int tt = 0; tt < 2; tt++) {
            int idx = tid + tt * 256;         // 0..511 chunks (16 per row)
            int row = idx >> 4;
            int c4  = (idx & 15) * 4;
            int kp  = t * KT + row;
            int kidx = (kp < cnt) ? __ldg(idxl + kp) : 0;
            cp16(ksb[buf] + (row * 68 + c4) * 4, kbh + (size_t)kidx * DK_ + c4);
            cp16(vsb[buf] + (row * 72 + c4) * 4, vbh + (size_t)kidx * DV_ + c4);
        }
        cp_commit();
    };

    issue_tile(0, 0);

    // Q fragments direct from gmem (fp32), scaled by 1/8, hi/lo split
    uint32_t qhi[8][4], qlo[8][4];
    {
        const int r0 = qb + warp * 16 + g;
        const int r1 = r0 + 8;
#pragma unroll
        for (int kt = 0; kt < 8; kt++) {
            float f0 = qbh[(size_t)r0 * DK_ + kt * 8 + tig]     * 0.125f;
            float f1 = qbh[(size_t)r1 * DK_ + kt * 8 + tig]     * 0.125f;
            float f2 = qbh[(size_t)r0 * DK_ + kt * 8 + tig + 4] * 0.125f;
            float f3 = qbh[(size_t)r1 * DK_ + kt * 8 + tig + 4] * 0.125f;
            float h0 = to_tf32(f0), h1 = to_tf32(f1), h2 = to_tf32(f2), h3 = to_tf32(f3);
            qhi[kt][0] = __float_as_uint(h0);
            qhi[kt][1] = __float_as_uint(h1);
            qhi[kt][2] = __float_as_uint(h2);
            qhi[kt][3] = __float_as_uint(h3);
            qlo[kt][0] = __float_as_uint(to_tf32(f0 - h0));
            qlo[kt][1] = __float_as_uint(to_tf32(f1 - h1));
            qlo[kt][2] = __float_as_uint(to_tf32(f2 - h2));
            qlo[kt][3] = __float_as_uint(to_tf32(f3 - h3));
        }
    }

    float m0 = -1e30f, m1 = -1e30f, l0 = 0.f, l1 = 0.f;
    float o[8][4];
#pragma unroll
    for (int nt = 0; nt < 8; nt++)
#pragma unroll
        for (int r = 0; r < 4; r++) o[nt][r] = 0.f;

    for (int t = 0; t < nTiles; t++) {
        const int kt0 = t * KT;
        if (t + 1 < nTiles) issue_tile(t + 1, (t + 1) & 1);
        else cp_commit();
        cp_wait<1>();
        __syncthreads();

        const int buf = t & 1;
        const uint32_t ksbb = ksb[buf];
        const float* vs = v_s[buf];

        // ---- QK^T : per-warp 16x32 scores (Q hi/lo compensated, K via ldmatrix) ----
        float s[4][4];
#pragma unroll
        for (int nt = 0; nt < 4; nt++)
#pragma unroll
            for (int r = 0; r < 4; r++) s[nt][r] = 0.f;

#pragma unroll
        for (int kt = 0; kt < 8; kt++) {
            uint32_t bb[4][2];
#pragma unroll
            for (int ntp = 0; ntp < 4; ntp += 2) {
                ldsm_x4(bb[ntp][0], bb[ntp][1], bb[ntp + 1][0], bb[ntp + 1][1],
                        ksbb + (uint32_t)((ntp * 8 * 68 + kt * 8) * 4) + koff);
            }
#pragma unroll
            for (int nt = 0; nt < 4; nt++) {
                mma_tf32(s[nt][0], s[nt][1], s[nt][2], s[nt][3],
                         qhi[kt][0], qhi[kt][1], qhi[kt][2], qhi[kt][3],
                         bb[nt][0], bb[nt][1]);
                mma_tf32(s[nt][0], s[nt][1], s[nt][2], s[nt][3],
                         qlo[kt][0], qlo[kt][1], qlo[kt][2], qlo[kt][3],
                         bb[nt][0], bb[nt][1]);
            }
        }

        // tail mask via select (padded rows must not win the max)
#pragma unroll
        for (int nt = 0; nt < 4; nt++) {
            int c0 = kt0 + nt * 8 + 2 * tig;
            int c1 = c0 + 1;
            if (c0 >= cnt) { s[nt][0] = -1e30f; s[nt][2] = -1e30f; }
            if (c1 >= cnt) { s[nt][1] = -1e30f; s[nt][3] = -1e30f; }
        }

        // ---- online softmax (rows g, g+8) ----
        float tm0 = -1e30f, tm1 = -1e30f;
#pragma unroll
        for (int nt = 0; nt < 4; nt++) {
            tm0 = fmaxf(tm0, fmaxf(s[nt][0], s[nt][1]));
            tm1 = fmaxf(tm1, fmaxf(s[nt][2], s[nt][3]));
        }
        tm0 = fmaxf(tm0, __shfl_xor_sync(0xffffffffu, tm0, 1));
        tm0 = fmaxf(tm0, __shfl_xor_sync(0xffffffffu, tm0, 2));
        tm1 = fmaxf(tm1, __shfl_xor_sync(0xffffffffu, tm1, 1));
        tm1 = fmaxf(tm1, __shfl_xor_sync(0xffffffffu, tm1, 2));
        float nm0 = fmaxf(m0, tm0);
        float nm1 = fmaxf(m1, tm1);
        float corr0 = __expf(m0 - nm0);
        float corr1 = __expf(m1 - nm1);
        m0 = nm0; m1 = nm1;

        float pr[4][4];
        float rs0 = 0.f, rs1 = 0.f;
#pragma unroll
        for (int nt = 0; nt < 4; nt++) {
            float p0 = __expf(s[nt][0] - nm0);
            float p1 = __expf(s[nt][1] - nm0);
            float p2 = __expf(s[nt][2] - nm1);
            float p3 = __expf(s[nt][3] - nm1);
            rs0 += p0 + p1;
            rs1 += p2 + p3;
            pr[nt][0] = to_tf32(p0);
            pr[nt][1] = to_tf32(p1);
            pr[nt][2] = to_tf32(p2);
            pr[nt][3] = to_tf32(p3);
        }
        rs0 += __shfl_xor_sync(0xffffffffu, rs0, 1);
        rs0 += __shfl_xor_sync(0xffffffffu, rs0, 2);
        rs1 += __shfl_xor_sync(0xffffffffu, rs1, 1);
        rs1 += __shfl_xor_sync(0xffffffffu, rs1, 2);
        l0 = l0 * corr0 + rs0;
        l1 = l1 * corr1 + rs1;

#pragma unroll
        for (int nt = 0; nt < 8; nt++) {
            o[nt][0] *= corr0; o[nt][1] *= corr0;
            o[nt][2] *= corr1; o[nt][3] *= corr1;
        }

        // ---- PV : o(16x64) += P(16x32) @ V(32x64) ----
        // A-frags of P built by warp shuffles from the C-layout registers.
#pragma unroll
        for (int kk = 0; kk < 4; kk++) {
            float x0 = __shfl_sync(0xffffffffu, pr[kk][0], psrc0);
            float x1 = __shfl_sync(0xffffffffu, pr[kk][1], psrc0);
            float x2 = __shfl_sync(0xffffffffu, pr[kk][2], psrc0);
            float x3 = __shfl_sync(0xffffffffu, pr[kk][3], psrc0);
            float y0 = __shfl_sync(0xffffffffu, pr[kk][0], psrc1);
            float y1 = __shfl_sync(0xffffffffu, pr[kk][1], psrc1);
            float y2 = __shfl_sync(0xffffffffu, pr[kk][2], psrc1);
            float y3 = __shfl_sync(0xffffffffu, pr[kk][3], psrc1);
            uint32_t a0 = __float_as_uint(podd ? x1 : x0);   // P[g,    kk*8+tig]
            uint32_t a1 = __float_as_uint(podd ? x3 : x2);   // P[g+8,  kk*8+tig]
            uint32_t a2 = __float_as_uint(podd ? y1 : y0);   // P[g,    kk*8+tig+4]
            uint32_t a3 = __float_as_uint(podd ? y3 : y2);   // P[g+8,  kk*8+tig+4]
#pragma unroll
            for (int nt = 0; nt < 8; nt++) {
                uint32_t bv0 = __float_as_uint(vs[(kk * 8 + tig) * 72 + nt * 8 + g]);
                uint32_t bv1 = __float_as_uint(vs[(kk * 8 + tig + 4) * 72 + nt * 8 + g]);
                mma_tf32(o[nt][0], o[nt][1], o[nt][2], o[nt][3],
                         a0, a1, a2, a3, bv0, bv1);
            }
        }
        __syncthreads();
    }

    // ---- finalize: out[b, s, h*64 + d], tf32-rounded for the out-GEMM ----
    float inv0 = 1.f / l0;
    float inv1 = 1.f / l1;
    int s0 = qb + warp * 16 + g;
    int s1 = s0 + 8;
#pragma unroll
    for (int nt = 0; nt < 8; nt++) {
        int d = nt * 8 + 2 * tig;
        float2 w0; w0.x = to_tf32(o[nt][0] * inv0); w0.y = to_tf32(o[nt][1] * inv0);
        float2 w1; w1.x = to_tf32(o[nt][2] * inv1); w1.y = to_tf32(o[nt][3] * inv1);
        *(float2*)&out[((size_t)(b * S_ + s0) * H_ + h) * DV_ + d] = w0;
        *(float2*)&out[((size_t)(b * S_ + s1) * H_ + h) * DV_ + d] = w1;
    }
}

// ---------------------------------------------------------------------------
extern "C" void kernel_launch(void* const* d_in, const int* in_sizes, int n_in,
                              void* d_out, int out_size)
{
    const float* query = (const float*)d_in[0];
    const float* key   = (const float*)d_in[1];
    const float* value = (const float*)d_in[2];
    const int*   amask = (const int*)d_in[3];
    const float* wq = (const float*)d_in[4];
    const float* bq = (const float*)d_in[5];
    const float* wk = (const float*)d_in[6];
    const float* bk = (const float*)d_in[7];
    const float* wv = (const float*)d_in[8];
    const float* bv = (const float*)d_in[9];
    const float* wo = (const float*)d_in[10];
    const float* bo = (const float*)d_in[11];
    float* out = (float*)d_out;

    float *gq, *gk, *gv, *ga, *gqc, *gkc, *gvc, *gwq, *gwk, *gwv, *gwo;
    cudaGetSymbolAddress((void**)&gq,  g_q);
    cudaGetSymbolAddress((void**)&gk,  g_k);
    cudaGetSymbolAddress((void**)&gv,  g_v);
    cudaGetSymbolAddress((void**)&ga,  g_a);
    cudaGetSymbolAddress((void**)&gqc, g_qc);
    cudaGetSymbolAddress((void**)&gkc, g_kc);
    cudaGetSymbolAddress((void**)&gvc, g_vc);
    cudaGetSymbolAddress((void**)&gwq, g_wqr);
    cudaGetSymbolAddress((void**)&gwk, g_wkr);
    cudaGetSymbolAddress((void**)&gwv, g_wvr);
    cudaGetSymbolAddress((void**)&gwo, g_wor);

    cudaFuncSetAttribute(gemm_tc<0>, cudaFuncAttributeMaxDynamicSharedMemorySize, GEMM_SMEM);
    cudaFuncSetAttribute(gemm_tc<1>, cudaFuncAttributeMaxDynamicSharedMemorySize, GEMM_SMEM);

    const int M = B_ * S_;       // 8192
    const int N = H_ * DK_;      // 1024
    const int K = D_;            // 1024

    compact_k<<<B_, 32>>>(amask);

    // pre-round inputs (3 big tensors) and weights (4 tensors) to tf32
    round_k<<<dim3(1024, 3), 256>>>(query, key, value, query,
                                    gqc, gkc, gvc, gqc, (B_ * S_ * D_) / 4);
    round_k<<<dim3(128, 4), 256>>>(wq, wk, wv, wo,
                                   gwq, gwk, gwv, gwo, (D_ * 1024) / 4);

    dim3 ggrid(N / 128, M / 128, 3);
    gemm_tc<0><<<ggrid, 256, GEMM_SMEM>>>(gqc, gkc, gvc,
                                          gwq, gwk, gwv,
                                          bq, bk, bv,
                                          gq, gk, gv, M, N, K);

    dim3 agrid(S_ / 128, H_, B_);
    attn_tc<<<agrid, 256>>>(gq, gk, gv, ga);

    gemm_tc<1><<<dim3(1024 / 128, M / 128, 1), 256, GEMM_SMEM>>>(ga, ga, ga,
                                                                 gwo, gwo, gwo,
                                                                 bo, bo, bo,
                                                                 out, out, out, M, 1024, H_ * DV_);
}

// round 17
// speedup vs baseline: 1.2402x; 1.2402x over previous
#include <cuda_runtime.h>
#include <math.h>
#include <stdint.h>

#define B_  4
#define S_  2048
#define D_  1024
#define H_  16
#define DK_ 64
#define DV_ 64

// Scratch (alloc-free rule: __device__ globals)
__device__ float g_q[B_*H_*S_*DK_];   // [B,H,S,DK] fp32 (raw)
__device__ float g_k[B_*H_*S_*DK_];   // [B,H,S,DK] tf32-rounded
__device__ float g_v[B_*H_*S_*DV_];   // [B,H,S,DV] tf32-rounded
__device__ float g_a[B_*S_*H_*DV_];   // [B,S,H*DV] tf32-rounded
__device__ float g_qc[B_*S_*D_];      // rounded copy of query
__device__ float g_kc[B_*S_*D_];      // rounded copy of key
__device__ float g_vc[B_*S_*D_];      // rounded copy of value
__device__ float g_wqt[D_*H_*DK_];    // W^T [N][K], tf32-rounded
__device__ float g_wkt[D_*H_*DK_];
__device__ float g_wvt[D_*H_*DV_];
__device__ float g_wot[H_*DV_*D_];
__device__ int   g_idx[B_*S_];        // compacted unmasked key indices
__device__ int   g_cnt[B_];           // count per batch

__device__ __forceinline__ float to_tf32(float x) {
    float r;
    asm("cvt.rna.tf32.f32 %0, %1;" : "=f"(r) : "f"(x));
    return r;
}

__device__ __forceinline__ void mma_tf32(float& d0, float& d1, float& d2, float& d3,
                                         uint32_t a0, uint32_t a1, uint32_t a2, uint32_t a3,
                                         uint32_t b0, uint32_t b1)
{
    asm volatile(
        "mma.sync.aligned.m16n8k8.row.col.f32.tf32.tf32.f32 "
        "{%0,%1,%2,%3}, {%4,%5,%6,%7}, {%8,%9}, {%0,%1,%2,%3};"
        : "+f"(d0), "+f"(d1), "+f"(d2), "+f"(d3)
        : "r"(a0), "r"(a1), "r"(a2), "r"(a3), "r"(b0), "r"(b1));
}

__device__ __forceinline__ void ldsm_x4(uint32_t& r0, uint32_t& r1, uint32_t& r2, uint32_t& r3,
                                        uint32_t addr)
{
    asm volatile("ldmatrix.sync.aligned.m8n8.x4.shared.b16 {%0,%1,%2,%3}, [%4];"
                 : "=r"(r0), "=r"(r1), "=r"(r2), "=r"(r3) : "r"(addr));
}

__device__ __forceinline__ void cp16(uint32_t dst_smem, const void* src) {
    asm volatile("cp.async.cg.shared.global [%0], [%1], 16;" :: "r"(dst_smem), "l"(src));
}
__device__ __forceinline__ void cp_commit() {
    asm volatile("cp.async.commit_group;");
}
template<int N>
__device__ __forceinline__ void cp_wait() {
    asm volatile("cp.async.wait_group %0;" :: "n"(N));
}

// ---------------------------------------------------------------------------
// Mask compaction: one warp per batch. Keys with mask==0 survive.
// ---------------------------------------------------------------------------
__global__ void compact_k(const int* __restrict__ mask)
{
    const int b = blockIdx.x;
    const int lane = threadIdx.x;
    int c = 0;
    for (int base = 0; base < S_; base += 32) {
        int mv = mask[b * S_ + base + lane];
        unsigned ball = __ballot_sync(0xffffffffu, mv == 0);
        int rank = __popc(ball & ((1u << lane) - 1));
        if (mv == 0) g_idx[b * S_ + c + rank] = base + lane;
        c += __popc(ball);
    }
    if (lane == 0) g_cnt[b] = c;
}

// ---------------------------------------------------------------------------
// Pre-round inputs to tf32 (rna), vectorized. blockIdx.y selects the tensor.
// ---------------------------------------------------------------------------
__global__ void round_k(const float* __restrict__ s0, const float* __restrict__ s1,
                        const float* __restrict__ s2,
                        float* __restrict__ d0, float* __restrict__ d1,
                        float* __restrict__ d2, int n4)
{
    const int z = blockIdx.y;
    const float* s = (z == 0) ? s0 : (z == 1) ? s1 : s2;
    float*       d = (z == 0) ? d0 : (z == 1) ? d1 : d2;
    const int stride = gridDim.x * blockDim.x;
    for (int i = blockIdx.x * blockDim.x + threadIdx.x; i < n4; i += stride) {
        float4 v = ((const float4*)s)[i];
        v.x = to_tf32(v.x); v.y = to_tf32(v.y);
        v.z = to_tf32(v.z); v.w = to_tf32(v.w);
        ((float4*)d)[i] = v;
    }
}

// ---------------------------------------------------------------------------
// Transpose + round weights: Wt[n][k] = rna(W[k][n]). 1024x1024 each.
// ---------------------------------------------------------------------------
__global__ void transp_round_k(const float* __restrict__ s0, const float* __restrict__ s1,
                               const float* __restrict__ s2, const float* __restrict__ s3,
                               float* __restrict__ d0, float* __restrict__ d1,
                               float* __restrict__ d2, float* __restrict__ d3)
{
    const int z = blockIdx.z;
    const float* s = (z == 0) ? s0 : (z == 1) ? s1 : (z == 2) ? s2 : s3;
    float*       d = (z == 0) ? d0 : (z == 1) ? d1 : (z == 2) ? d2 : d3;
    __shared__ float t[32][33];
    const int bx = blockIdx.x * 32, by = blockIdx.y * 32;
    const int tx = threadIdx.x, ty = threadIdx.y;   // 32 x 8
#pragma unroll
    for (int i = 0; i < 32; i += 8)
        t[ty + i][tx] = s[(size_t)(by + ty + i) * 1024 + bx + tx];
    __syncthreads();
#pragma unroll
    for (int i = 0; i < 32; i += 8)
        d[(size_t)(bx + ty + i) * 1024 + by + tx] = to_tf32(t[tx][ty + i]);
}

// ---------------------------------------------------------------------------
// tf32 tensor-core GEMM. Inputs PRE-ROUNDED; weights PRE-TRANSPOSED [N][K].
// 3-stage cp.async pipeline, k-step 16, ONE __syncthreads per k-iter.
// A and B staged identically: [row][16] floats, XOR swizzle chunk^=swz(row).
// BOTH operand fragments via ldmatrix (A: 4x ldsm_x4, B: 2x ldsm_x4 / k-slice).
// Block tile 128x128, 256 threads = 8 warps (2x4), warp tile 64x32.
// MODE 0: fused QKV (z selects set), scatter-store [B,H,S,64];
//         z=1,2 (K,V) stored tf32-rounded, z=0 (Q) raw fp32.
// MODE 1: single GEMM, row-major store.
// ---------------------------------------------------------------------------
template<int MODE>
__global__ __launch_bounds__(256, 2)
void gemm_tc(const float* __restrict__ A0, const float* __restrict__ A1,
             const float* __restrict__ A2,
             const float* __restrict__ W0, const float* __restrict__ W1,
             const float* __restrict__ W2,
             const float* __restrict__ b0p, const float* __restrict__ b1p,
             const float* __restrict__ b2p,
             float* __restrict__ C0, float* __restrict__ C1, float* __restrict__ C2,
             int M, int N, int K)
{
    __shared__ __align__(16) float As[3][128 * 16];
    __shared__ __align__(16) float Bs[3][128 * 16];

    const int z = (MODE == 0) ? blockIdx.z : 0;
    const float* A    = (z == 0) ? A0 : (z == 1) ? A1 : A2;
    const float* W    = (z == 0) ? W0 : (z == 1) ? W1 : W2;   // [N][K]
    const float* bias = (z == 0) ? b0p : (z == 1) ? b1p : b2p;
    float*       C    = (z == 0) ? C0 : (z == 1) ? C1 : C2;

    const int tid  = threadIdx.x;
    const int warp = tid >> 5;
    const int lane = tid & 31;
    const int g    = lane >> 2;
    const int tig  = lane & 3;
    const int wr   = warp >> 2;
    const int wc   = warp & 3;

    const int rBase = blockIdx.y * 128;
    const int cBase = blockIdx.x * 128;

    uint32_t asb[3], bsb[3];
#pragma unroll
    for (int s = 0; s < 3; s++) {
        asb[s] = (uint32_t)__cvta_generic_to_shared(As[s]);
        bsb[s] = (uint32_t)__cvta_generic_to_shared(Bs[s]);
    }

    // A ldmatrix lane mapping: m16 = row within 16-row tile, khalf = chunk parity
    const int m16   = lane & 15;
    const int khalf = lane >> 4;
    const int aswz  = (m16 + (m16 >> 2)) & 3;

    // B ldmatrix lane mapping (attention-style): 8-col groups, chunk parity
    const int brow_off = ((lane >> 4) << 3) + (lane & 7);  // 0..15
    const int bpar     = (lane >> 3) & 1;
    const int brow0    = wc * 32 + brow_off;               // ntp=0 tile pair
    const int brow1    = brow0 + 16;                       // ntp=2 tile pair
    const int bswz0    = (brow0 + (brow0 >> 2)) & 3;
    const int bswz1    = (brow1 + (brow1 >> 2)) & 3;

    auto issue = [&](int k0, int buf) {
#pragma unroll
        for (int j = 0; j < 2; j++) {
            int idx = tid + j * 256;          // 512 chunks of 16B each matrix
            int r   = idx >> 2;
            int qq  = idx & 3;
            int swr = (r + (r >> 2)) & 3;
            uint32_t off = (uint32_t)((r * 16 + ((qq ^ swr) << 2)) << 2);
            cp16(asb[buf] + off, A + (size_t)(rBase + r) * K + k0 + qq * 4);
            cp16(bsb[buf] + off, W + (size_t)(cBase + r) * K + k0 + qq * 4);
        }
        cp_commit();
    };

    float acc[4][4][4];
#pragma unroll
    for (int mt = 0; mt < 4; mt++)
#pragma unroll
        for (int nt = 0; nt < 4; nt++)
#pragma unroll
            for (int r = 0; r < 4; r++) acc[mt][nt][r] = 0.f;

    auto compute = [&](int buf) {
        const uint32_t as = asb[buf];
        const uint32_t bs = bsb[buf];
#pragma unroll
        for (int ks = 0; ks < 2; ks++) {
            uint32_t a[4][4];
#pragma unroll
            for (int mt = 0; mt < 4; mt++) {
                int row = wr * 64 + mt * 16 + m16;
                ldsm_x4(a[mt][0], a[mt][1], a[mt][2], a[mt][3],
                        as + (uint32_t)(((row * 16) + (((2 * ks + khalf) ^ aswz) << 2)) << 2));
            }
            uint32_t b[4][2];
            ldsm_x4(b[0][0], b[0][1], b[1][0], b[1][1],
                    bs + (uint32_t)(((brow0 * 16) + (((2 * ks + bpar) ^ bswz0) << 2)) << 2));
            ldsm_x4(b[2][0], b[2][1], b[3][0], b[3][1],
                    bs + (uint32_t)(((brow1 * 16) + (((2 * ks + bpar) ^ bswz1) << 2)) << 2));
#pragma unroll
            for (int mt = 0; mt < 4; mt++)
#pragma unroll
                for (int nt = 0; nt < 4; nt++)
                    mma_tf32(acc[mt][nt][0], acc[mt][nt][1], acc[mt][nt][2], acc[mt][nt][3],
                             a[mt][0], a[mt][1], a[mt][2], a[mt][3],
                             b[nt][0], b[nt][1]);
        }
    };

    const int niter = K / 16;
    issue(0, 0);
    issue(16, 1);
    for (int i = 0; i < niter; i++) {
        cp_wait<1>();
        __syncthreads();
        compute(i % 3);
        if (i + 2 < niter) issue((i + 2) * 16, (i + 2) % 3);
        else cp_commit();
    }

    // epilogue
#pragma unroll
    for (int mt = 0; mt < 4; mt++) {
#pragma unroll
        for (int nt = 0; nt < 4; nt++) {
#pragma unroll
            for (int half = 0; half < 2; half++) {
                int r = rBase + wr * 64 + mt * 16 + g + half * 8;
                int c = cBase + wc * 32 + nt * 8 + tig * 2;
                float v0 = acc[mt][nt][half * 2 + 0] + bias[c];
                float v1 = acc[mt][nt][half * 2 + 1] + bias[c + 1];
                if (MODE == 0) {
                    if (z != 0) { v0 = to_tf32(v0); v1 = to_tf32(v1); }
                    int bb = r >> 11;
                    int s  = r & 2047;
                    int h  = c >> 6;
                    int dk = c & 63;
                    size_t base = (((size_t)(bb * H_ + h) * S_) + s) * DK_ + dk;
                    C[base]     = v0;
                    C[base + 1] = v1;
                } else {
                    C[(size_t)r * N + c]     = v0;
                    C[(size_t)r * N + c + 1] = v1;
                }
            }
        }
    }
}

// ---------------------------------------------------------------------------
// Tensor-core flash attention over COMPACTED keys.
// 256 threads / 8 warps, 128 q-rows per block (16 per warp).
// tf32 MMA; Q single-rounded (no lo-compensation), K/V pre-rounded,
// K fragments via ldmatrix. P (C-layout) -> A-layout by warp shuffles.
// cp.async double-buffered K/V gather.
// ---------------------------------------------------------------------------
#define KT 32

__global__ __launch_bounds__(256)
void attn_tc(const float* __restrict__ q, const float* __restrict__ k,
             const float* __restrict__ v, float* __restrict__ out)
{
    __shared__ __align__(16) float k_s[2][KT * 68];
    __shared__ __align__(16) float v_s[2][KT * 72];

    const int tid  = threadIdx.x;
    const int warp = tid >> 5;
    const int lane = tid & 31;
    const int g    = lane >> 2;
    const int tig  = lane & 3;

    const int qb = blockIdx.x * 128;
    const int h  = blockIdx.y;
    const int b  = blockIdx.z;

    const int  cnt  = g_cnt[b];
    const int* idxl = g_idx + b * S_;

    const float* qbh = q + ((size_t)(b * H_ + h) * S_) * DK_;
    const float* kbh = k + ((size_t)(b * H_ + h) * S_) * DK_;
    const float* vbh = v + ((size_t)(b * H_ + h) * S_) * DV_;

    const uint32_t ksb[2] = { (uint32_t)__cvta_generic_to_shared(k_s[0]),
                              (uint32_t)__cvta_generic_to_shared(k_s[1]) };
    const uint32_t vsb[2] = { (uint32_t)__cvta_generic_to_shared(v_s[0]),
                              (uint32_t)__cvta_generic_to_shared(v_s[1]) };

    const uint32_t koff = (((((lane >> 4) << 3) + (lane & 7)) * 68) + (((lane >> 3) & 1) << 2)) * 4;

    const int psrc0 = (lane & ~3) | (tig >> 1);
    const int psrc1 = psrc0 + 2;
    const bool podd = (tig & 1);

    const int nTiles = (cnt + KT - 1) / KT;

    auto issue_tile = [&](int t, int buf) {
#pragma unroll
        for (int tt = 0; tt < 2; tt++) {
            int idx = tid + tt * 256;
            int row = idx >> 4;
            int c4  = (idx & 15) * 4;
            int kp  = t * KT + row;
            int kidx = (kp < cnt) ? __ldg(idxl + kp) : 0;
            cp16(ksb[buf] + (row * 68 + c4) * 4, kbh + (size_t)kidx * DK_ + c4);
            cp16(vsb[buf] + (row * 72 + c4) * 4, vbh + (size_t)kidx * DV_ + c4);
        }
        cp_commit();
    };

    issue_tile(0, 0);

    // Q fragments direct from gmem (fp32), scaled by 1/8, single-rounded
    uint32_t qf[8][4];
    {
        const int r0 = qb + warp * 16 + g;
        const int r1 = r0 + 8;
#pragma unroll
        for (int kt = 0; kt < 8; kt++) {
            qf[kt][0] = __float_as_uint(to_tf32(qbh[(size_t)r0 * DK_ + kt * 8 + tig]     * 0.125f));
            qf[kt][1] = __float_as_uint(to_tf32(qbh[(size_t)r1 * DK_ + kt * 8 + tig]     * 0.125f));
            qf[kt][2] = __float_as_uint(to_tf32(qbh[(size_t)r0 * DK_ + kt * 8 + tig + 4] * 0.125f));
            qf[kt][3] = __float_as_uint(to_tf32(qbh[(size_t)r1 * DK_ + kt * 8 + tig + 4] * 0.125f));
        }
    }

    float m0 = -1e30f, m1 = -1e30f, l0 = 0.f, l1 = 0.f;
    float o[8][4];
#pragma unroll
    for (int nt = 0; nt < 8; nt++)
#pragma unroll
        for (int r = 0; r < 4; r++) o[nt][r] = 0.f;

    for (int t = 0; t < nTiles; t++) {
        const int kt0 = t * KT;
        if (t + 1 < nTiles) issue_tile(t + 1, (t + 1) & 1);
        else cp_commit();
        cp_wait<1>();
        __syncthreads();

        const int buf = t & 1;
        const uint32_t ksbb = ksb[buf];
        const float* vs = v_s[buf];

        // ---- QK^T : per-warp 16x32 scores (K via ldmatrix) ----
        float s[4][4];
#pragma unroll
        for (int nt = 0; nt < 4; nt++)
#pragma unroll
            for (int r = 0; r < 4; r++) s[nt][r] = 0.f;

#pragma unroll
        for (int kt = 0; kt < 8; kt++) {
            uint32_t bb[4][2];
#pragma unroll
            for (int ntp = 0; ntp < 4; ntp += 2) {
                ldsm_x4(bb[ntp][0], bb[ntp][1], bb[ntp + 1][0], bb[ntp + 1][1],
                        ksbb + (uint32_t)((ntp * 8 * 68 + kt * 8) * 4) + koff);
            }
#pragma unroll
            for (int nt = 0; nt < 4; nt++)
                mma_tf32(s[nt][0], s[nt][1], s[nt][2], s[nt][3],
                         qf[kt][0], qf[kt][1], qf[kt][2], qf[kt][3],
                         bb[nt][0], bb[nt][1]);
        }

        // tail mask via select (padded rows must not win the max)
#pragma unroll
        for (int nt = 0; nt < 4; nt++) {
            int c0 = kt0 + nt * 8 + 2 * tig;
            int c1 = c0 + 1;
            if (c0 >= cnt) { s[nt][0] = -1e30f; s[nt][2] = -1e30f; }
            if (c1 >= cnt) { s[nt][1] = -1e30f; s[nt][3] = -1e30f; }
        }

        // ---- online softmax (rows g, g+8) ----
        float tm0 = -1e30f, tm1 = -1e30f;
#pragma unroll
        for (int nt = 0; nt < 4; nt++) {
            tm0 = fmaxf(tm0, fmaxf(s[nt][0], s[nt][1]));
            tm1 = fmaxf(tm1, fmaxf(s[nt][2], s[nt][3]));
        }
        tm0 = fmaxf(tm0, __shfl_xor_sync(0xffffffffu, tm0, 1));
        tm0 = fmaxf(tm0, __shfl_xor_sync(0xffffffffu, tm0, 2));
        tm1 = fmaxf(tm1, __shfl_xor_sync(0xffffffffu, tm1, 1));
        tm1 = fmaxf(tm1, __shfl_xor_sync(0xffffffffu, tm1, 2));
        float nm0 = fmaxf(m0, tm0);
        float nm1 = fmaxf(m1, tm1);
        float corr0 = __expf(m0 - nm0);
        float corr1 = __expf(m1 - nm1);
        m0 = nm0; m1 = nm1;

        float pr[4][4];
        float rs0 = 0.f, rs1 = 0.f;
#pragma unroll
        for (int nt = 0; nt < 4; nt++) {
            float p0 = __expf(s[nt][0] - nm0);
            float p1 = __expf(s[nt][1] - nm0);
            float p2 = __expf(s[nt][2] - nm1);
            float p3 = __expf(s[nt][3] - nm1);
            rs0 += p0 + p1;
            rs1 += p2 + p3;
            pr[nt][0] = to_tf32(p0);
            pr[nt][1] = to_tf32(p1);
            pr[nt][2] = to_tf32(p2);
            pr[nt][3] = to_tf32(p3);
        }
        rs0 += __shfl_xor_sync(0xffffffffu, rs0, 1);
        rs0 += __shfl_xor_sync(0xffffffffu, rs0, 2);
        rs1 += __shfl_xor_sync(0xffffffffu, rs1, 1);
        rs1 += __shfl_xor_sync(0xffffffffu, rs1, 2);
        l0 = l0 * corr0 + rs0;
        l1 = l1 * corr1 + rs1;

#pragma unroll
        for (int nt = 0; nt < 8; nt++) {
            o[nt][0] *= corr0; o[nt][1] *= corr0;
            o[nt][2] *= corr1; o[nt][3] *= corr1;
        }

        // ---- PV : o(16x64) += P(16x32) @ V(32x64) ----
#pragma unroll
        for (int kk = 0; kk < 4; kk++) {
            float x0 = __shfl_sync(0xffffffffu, pr[kk][0], psrc0);
            float x1 = __shfl_sync(0xffffffffu, pr[kk][1], psrc0);
            float x2 = __shfl_sync(0xffffffffu, pr[kk][2], psrc0);
            float x3 = __shfl_sync(0xffffffffu, pr[kk][3], psrc0);
            float y0 = __shfl_sync(0xffffffffu, pr[kk][0], psrc1);
            float y1 = __shfl_sync(0xffffffffu, pr[kk][1], psrc1);
            float y2 = __shfl_sync(0xffffffffu, pr[kk][2], psrc1);
            float y3 = __shfl_sync(0xffffffffu, pr[kk][3], psrc1);
            uint32_t a0 = __float_as_uint(podd ? x1 : x0);
            uint32_t a1 = __float_as_uint(podd ? x3 : x2);
            uint32_t a2 = __float_as_uint(podd ? y1 : y0);
            uint32_t a3 = __float_as_uint(podd ? y3 : y2);
#pragma unroll
            for (int nt = 0; nt < 8; nt++) {
                uint32_t bv0 = __float_as_uint(vs[(kk * 8 + tig) * 72 + nt * 8 + g]);
                uint32_t bv1 = __float_as_uint(vs[(kk * 8 + tig + 4) * 72 + nt * 8 + g]);
                mma_tf32(o[nt][0], o[nt][1], o[nt][2], o[nt][3],
                         a0, a1, a2, a3, bv0, bv1);
            }
        }
        __syncthreads();
    }

    // ---- finalize: out[b, s, h*64 + d], tf32-rounded for the out-GEMM ----
    float inv0 = 1.f / l0;
    float inv1 = 1.f / l1;
    int s0 = qb + warp * 16 + g;
    int s1 = s0 + 8;
#pragma unroll
    for (int nt = 0; nt < 8; nt++) {
        int d = nt * 8 + 2 * tig;
        float2 w0; w0.x = to_tf32(o[nt][0] * inv0); w0.y = to_tf32(o[nt][1] * inv0);
        float2 w1; w1.x = to_tf32(o[nt][2] * inv1); w1.y = to_tf32(o[nt][3] * inv1);
        *(float2*)&out[((size_t)(b * S_ + s0) * H_ + h) * DV_ + d] = w0;
        *(float2*)&out[((size_t)(b * S_ + s1) * H_ + h) * DV_ + d] = w1;
    }
}

// ---------------------------------------------------------------------------
extern "C" void kernel_launch(void* const* d_in, const int* in_sizes, int n_in,
                              void* d_out, int out_size)
{
    const float* query = (const float*)d_in[0];
    const float* key   = (const float*)d_in[1];
    const float* value = (const float*)d_in[2];
    const int*   amask = (const int*)d_in[3];
    const float* wq = (const float*)d_in[4];
    const float* bq = (const float*)d_in[5];
    const float* wk = (const float*)d_in[6];
    const float* bk = (const float*)d_in[7];
    const float* wv = (const float*)d_in[8];
    const float* bv = (const float*)d_in[9];
    const float* wo = (const float*)d_in[10];
    const float* bo = (const float*)d_in[11];
    float* out = (float*)d_out;

    float *gq, *gk, *gv, *ga, *gqc, *gkc, *gvc, *gwq, *gwk, *gwv, *gwo;
    cudaGetSymbolAddress((void**)&gq,  g_q);
    cudaGetSymbolAddress((void**)&gk,  g_k);
    cudaGetSymbolAddress((void**)&gv,  g_v);
    cudaGetSymbolAddress((void**)&ga,  g_a);
    cudaGetSymbolAddress((void**)&gqc, g_qc);
    cudaGetSymbolAddress((void**)&gkc, g_kc);
    cudaGetSymbolAddress((void**)&gvc, g_vc);
    cudaGetSymbolAddress((void**)&gwq, g_wqt);
    cudaGetSymbolAddress((void**)&gwk, g_wkt);
    cudaGetSymbolAddress((void**)&gwv, g_wvt);
    cudaGetSymbolAddress((void**)&gwo, g_wot);

    const int M = B_ * S_;       // 8192
    const int N = H_ * DK_;      // 1024
    const int K = D_;            // 1024

    compact_k<<<B_, 32>>>(amask);

    // pre-round big inputs; transpose+round weights to [N][K]
    round_k<<<dim3(1024, 3), 256>>>(query, key, value,
                                    gqc, gkc, gvc, (B_ * S_ * D_) / 4);
    transp_round_k<<<dim3(32, 32, 4), dim3(32, 8)>>>(wq, wk, wv, wo,
                                                     gwq, gwk, gwv, gwo);

    dim3 ggrid(N / 128, M / 128, 3);
    gemm_tc<0><<<ggrid, 256>>>(gqc, gkc, gvc,
                               gwq, gwk, gwv,
                               bq, bk, bv,
                               gq, gk, gv, M, N, K);

    dim3 agrid(S_ / 128, H_, B_);
    attn_tc<<<agrid, 256>>>(gq, gk, gv, ga);

    gemm_tc<1><<<dim3(1024 / 128, M / 128, 1), 256>>>(ga, ga, ga,
                                                      gwo, gwo, gwo,
                                                      bo, bo, bo,
                                                      out, out, out, M, 1024, H_ * DV_);
}